// round 5
// baseline (speedup 1.0000x reference)
#include <cuda_runtime.h>
#include <cuda_bf16.h>
#include <cstdint>

// ---------------- scratch (device globals; no allocation allowed) ----------
#define MAX_N 100000
#define MAX_E 1600000
#define DF 128

__device__ float g_pooled[(size_t)MAX_N * DF];
__device__ float g_y1[(size_t)MAX_N * DF];
__device__ float g_stats[512];
__device__ float g_sf1[256];
__device__ float g_sf2[256];

// CSR scratch
__device__ int g_deg[MAX_N + 2];
__device__ int g_off[MAX_N + 2];
__device__ int g_cur[MAX_N + 2];
__device__ int g_blocksum[256];
__device__ int g_srcsorted[MAX_E];

// ==================== helpers ================================================

__device__ __forceinline__ void mma_bf16(float c[4], const uint32_t a[4],
                                         uint32_t b0, uint32_t b1) {
    asm volatile(
        "mma.sync.aligned.m16n8k16.row.col.f32.bf16.bf16.f32 "
        "{%0,%1,%2,%3}, {%4,%5,%6,%7}, {%8,%9}, {%0,%1,%2,%3};"
        : "+f"(c[0]), "+f"(c[1]), "+f"(c[2]), "+f"(c[3])
        : "r"(a[0]), "r"(a[1]), "r"(a[2]), "r"(a[3]), "r"(b0), "r"(b1));
}

__device__ __forceinline__ uint32_t pack_bf16x2(__nv_bfloat16 lo16, __nv_bfloat16 hi16) {
    uint32_t r = (uint32_t)__bfloat16_as_ushort(lo16) |
                 ((uint32_t)__bfloat16_as_ushort(hi16) << 16);
    return r;
}

// split two fp32 into packed bf16 hi + bf16 lo words
__device__ __forceinline__ void split2(float x0, float x1,
                                       uint32_t& hi, uint32_t& lo) {
    __nv_bfloat16 h0 = __float2bfloat16(x0);
    __nv_bfloat16 h1 = __float2bfloat16(x1);
    float r0 = x0 - __bfloat162float(h0);
    float r1 = x1 - __bfloat162float(h1);
    hi = pack_bf16x2(h0, h1);
    lo = pack_bf16x2(__float2bfloat16(r0), __float2bfloat16(r1));
}

// ==================== small utility kernels =================================

__global__ void init_kernel(int total) {
    int i = blockIdx.x * blockDim.x + threadIdx.x;
    if (i < 512) g_stats[i] = 0.f;
    if (i < total) g_deg[i] = 0;
}

__global__ void count_kernel(const int* __restrict__ edst, int E) {
    int i = blockIdx.x * blockDim.x + threadIdx.x;
    if (i < E) atomicAdd(&g_deg[edst[i]], 1);
}

__global__ void scan_block_sums(int total) {
    __shared__ int sdata[256];
    int b = blockIdx.x;
    int base = b * 1024;
    int t = threadIdx.x;
    int s = 0;
    for (int i = t; i < 1024; i += 256) {
        int g = base + i;
        s += (g < total) ? g_deg[g] : 0;
    }
    sdata[t] = s;
    __syncthreads();
    for (int o = 128; o > 0; o >>= 1) {
        if (t < o) sdata[t] += sdata[t + o];
        __syncthreads();
    }
    if (t == 0) g_blocksum[b] = sdata[0];
}

// merged: each block computes its own prefix of blocksums (NB < 1024)
__global__ void scan_final(int total) {
    __shared__ int sm[1024];
    __shared__ int sbase;
    int t = threadIdx.x;
    int b = blockIdx.x;
    if (t == 0) sbase = 0;
    __syncthreads();
    if (t < b) atomicAdd(&sbase, g_blocksum[t]);
    int g = b * 1024 + t;
    int x = (g < total) ? g_deg[g] : 0;
    sm[t] = x;
    __syncthreads();
#pragma unroll
    for (int o = 1; o < 1024; o <<= 1) {
        int v = (t >= o) ? sm[t - o] : 0;
        __syncthreads();
        sm[t] += v;
        __syncthreads();
    }
    int excl = sbase + sm[t] - x;
    if (g < total) {
        g_off[g] = excl;
        g_cur[g] = excl;
    }
}

__global__ void fill_kernel(const int* __restrict__ esrc,
                            const int* __restrict__ edst, int E) {
    int i = blockIdx.x * blockDim.x + threadIdx.x;
    if (i < E) {
        int d = edst[i];
        int pos = atomicAdd(&g_cur[d], 1);
        g_srcsorted[pos] = esrc[i];
    }
}

// ---------------- gather: pooled[i] = (1+eps)*h[i] + sum_{s in nbr(i)} h[s] -

__global__ void gather_kernel(const float4* __restrict__ h4,
                              const float* __restrict__ eps, int N) {
    int gwarp = (blockIdx.x * blockDim.x + threadIdx.x) >> 5;
    if (gwarp >= N) return;
    int lane = threadIdx.x & 31;
    int node = gwarp;

    float c = 1.f + eps[0];
    float4 self = __ldg(&h4[(long long)node * 32 + lane]);
    float4 acc;
    acc.x = self.x * c; acc.y = self.y * c; acc.z = self.z * c; acc.w = self.w * c;

    int begin = g_off[node];
    int end = g_off[node + 1];

    for (int j0 = begin; j0 < end; j0 += 32) {
        int cnt = min(32, end - j0);
        int myIdx = (lane < cnt) ? g_srcsorted[j0 + lane] : 0;
        int t = 0;
        for (; t + 4 <= cnt; t += 4) {
            int s0 = __shfl_sync(0xffffffff, myIdx, t + 0);
            int s1 = __shfl_sync(0xffffffff, myIdx, t + 1);
            int s2 = __shfl_sync(0xffffffff, myIdx, t + 2);
            int s3 = __shfl_sync(0xffffffff, myIdx, t + 3);
            float4 v0 = __ldg(&h4[(long long)s0 * 32 + lane]);
            float4 v1 = __ldg(&h4[(long long)s1 * 32 + lane]);
            float4 v2 = __ldg(&h4[(long long)s2 * 32 + lane]);
            float4 v3 = __ldg(&h4[(long long)s3 * 32 + lane]);
            acc.x += v0.x + v1.x; acc.y += v0.y + v1.y;
            acc.z += v0.z + v1.z; acc.w += v0.w + v1.w;
            acc.x += v2.x + v3.x; acc.y += v2.y + v3.y;
            acc.z += v2.z + v3.z; acc.w += v2.w + v3.w;
        }
        for (; t < cnt; t++) {
            int s = __shfl_sync(0xffffffff, myIdx, t);
            float4 v = __ldg(&h4[(long long)s * 32 + lane]);
            acc.x += v.x; acc.y += v.y; acc.z += v.z; acc.w += v.w;
        }
    }
    reinterpret_cast<float4*>(g_pooled)[(long long)node * 32 + lane] = acc;
}

// ==================== tensor-core GEMM (bf16 3-term split) ===================
// 256 threads (8 warps), block = 128 rows x 128 cols, K=128.
// Warp w: rows 16w..16w+15 (one m16 tile), 16 n8 tiles, acc = 64 regs.
// A fragments loaded from global (L2-resident) as float2 and split in regs.
// W^T (hi/lo bf16) staged in SMEM: [n][kword], stride 68 words (conflict-free).
// BN stats fused: shfl-reduce over g, lane g==0 atomicAdd to gsum.

#define WT_STRIDE 68
#define WT_WORDS (128 * WT_STRIDE)
#define GEMM_SMEM_BYTES (2 * WT_WORDS * 4)

template <bool TRANSFORM>
__global__ __launch_bounds__(256)
void gemm_bf16_kernel(const float* __restrict__ A,
                      const float* __restrict__ W,
                      const float* __restrict__ bias,
                      const float* __restrict__ sf,
                      float* __restrict__ Y,
                      float* __restrict__ gsum, int M) {
    extern __shared__ uint32_t smw[];
    uint32_t* Whi = smw;
    uint32_t* Wlo = smw + WT_WORDS;

    int tid = threadIdx.x;
    int lane = tid & 31;
    int warp = tid >> 5;
    int g = lane >> 2;
    int t = lane & 3;

    // ---- stage W^T hi/lo: thread owns column n, half the k range
    {
        int n = tid & 127;
        int kbeg = (tid >> 7) * 64;
#pragma unroll 8
        for (int k = kbeg; k < kbeg + 64; k += 2) {
            float w0 = __ldg(&W[(size_t)k * 128 + n]);
            float w1 = __ldg(&W[(size_t)(k + 1) * 128 + n]);
            uint32_t hi, lo;
            split2(w0, w1, hi, lo);
            Whi[n * WT_STRIDE + (k >> 1)] = hi;
            Wlo[n * WT_STRIDE + (k >> 1)] = lo;
        }
    }
    __syncthreads();

    int rowBase = blockIdx.x * 128 + warp * 16;
    int r0 = rowBase + g;
    int r1 = r0 + 8;
    bool v0 = r0 < M, v1 = r1 < M;

    float acc[16][4];
#pragma unroll
    for (int nt = 0; nt < 16; nt++)
#pragma unroll
        for (int q = 0; q < 4; q++) acc[nt][q] = 0.f;

#pragma unroll 1
    for (int ks = 0; ks < 8; ks++) {
        int kb = ks * 16;
        uint32_t ah[4], al[4];
        // fragment element loads: (row, col) pairs
        {
            int c0 = kb + 2 * t;
            int c1 = c0 + 8;
            float x00 = 0.f, x01 = 0.f, x10 = 0.f, x11 = 0.f;
            float x20 = 0.f, x21 = 0.f, x30 = 0.f, x31 = 0.f;
            if (v0) {
                float2 a = *reinterpret_cast<const float2*>(A + (size_t)r0 * 128 + c0);
                float2 b = *reinterpret_cast<const float2*>(A + (size_t)r0 * 128 + c1);
                x00 = a.x; x01 = a.y; x20 = b.x; x21 = b.y;
            }
            if (v1) {
                float2 a = *reinterpret_cast<const float2*>(A + (size_t)r1 * 128 + c0);
                float2 b = *reinterpret_cast<const float2*>(A + (size_t)r1 * 128 + c1);
                x10 = a.x; x11 = a.y; x30 = b.x; x31 = b.y;
            }
            if (TRANSFORM) {
                float s0 = __ldg(&sf[c0]),  h0 = __ldg(&sf[128 + c0]);
                float s1 = __ldg(&sf[c0 + 1]), h1 = __ldg(&sf[128 + c0 + 1]);
                float s2 = __ldg(&sf[c1]),  h2 = __ldg(&sf[128 + c1]);
                float s3 = __ldg(&sf[c1 + 1]), h3 = __ldg(&sf[128 + c1 + 1]);
                x00 = fmaxf(fmaf(x00, s0, h0), 0.f);
                x01 = fmaxf(fmaf(x01, s1, h1), 0.f);
                x10 = fmaxf(fmaf(x10, s0, h0), 0.f);
                x11 = fmaxf(fmaf(x11, s1, h1), 0.f);
                x20 = fmaxf(fmaf(x20, s2, h2), 0.f);
                x21 = fmaxf(fmaf(x21, s3, h3), 0.f);
                x30 = fmaxf(fmaf(x30, s2, h2), 0.f);
                x31 = fmaxf(fmaf(x31, s3, h3), 0.f);
                // OOB rows: transform of 0 gives relu(shift) != 0, but those
                // rows are never stored and contribute only to *their own*
                // accumulators which are discarded. Re-zero to keep stats exact.
                if (!v0) { x00 = 0.f; x01 = 0.f; x20 = 0.f; x21 = 0.f; }
                if (!v1) { x10 = 0.f; x11 = 0.f; x30 = 0.f; x31 = 0.f; }
            }
            split2(x00, x01, ah[0], al[0]);
            split2(x10, x11, ah[1], al[1]);
            split2(x20, x21, ah[2], al[2]);
            split2(x30, x31, ah[3], al[3]);
        }

        int wb = ks * 8;
#pragma unroll
        for (int nt = 0; nt < 16; nt++) {
            int n = nt * 8 + g;
            uint32_t b0h = Whi[n * WT_STRIDE + wb + t];
            uint32_t b1h = Whi[n * WT_STRIDE + wb + t + 4];
            uint32_t b0l = Wlo[n * WT_STRIDE + wb + t];
            uint32_t b1l = Wlo[n * WT_STRIDE + wb + t + 4];
            mma_bf16(acc[nt], ah, b0h, b1h);
            mma_bf16(acc[nt], al, b0h, b1h);
            mma_bf16(acc[nt], ah, b0l, b1l);
        }
    }

    // ---- epilogue: bias add, store, fused BN stats
#pragma unroll
    for (int nt = 0; nt < 16; nt++) {
        int col = nt * 8 + 2 * t;
        float bx = __ldg(&bias[col]);
        float by = __ldg(&bias[col + 1]);
        float y0 = acc[nt][0] + bx, y1 = acc[nt][1] + by;
        float y2 = acc[nt][2] + bx, y3 = acc[nt][3] + by;
        if (v0) {
            float2 v = {y0, y1};
            *reinterpret_cast<float2*>(Y + (size_t)r0 * 128 + col) = v;
        }
        if (v1) {
            float2 v = {y2, y3};
            *reinterpret_cast<float2*>(Y + (size_t)r1 * 128 + col) = v;
        }
        float s0 = (v0 ? y0 : 0.f) + (v1 ? y2 : 0.f);
        float s1 = (v0 ? y1 : 0.f) + (v1 ? y3 : 0.f);
        float q0 = (v0 ? y0 * y0 : 0.f) + (v1 ? y2 * y2 : 0.f);
        float q1 = (v0 ? y1 * y1 : 0.f) + (v1 ? y3 * y3 : 0.f);
        // reduce across g (lane bits 2..4)
#pragma unroll
        for (int m = 4; m <= 16; m <<= 1) {
            s0 += __shfl_xor_sync(0xffffffff, s0, m);
            s1 += __shfl_xor_sync(0xffffffff, s1, m);
            q0 += __shfl_xor_sync(0xffffffff, q0, m);
            q1 += __shfl_xor_sync(0xffffffff, q1, m);
        }
        if (g == 0) {
            atomicAdd(&gsum[col], s0);
            atomicAdd(&gsum[col + 1], s1);
            atomicAdd(&gsum[128 + col], q0);
            atomicAdd(&gsum[128 + col + 1], q1);
        }
    }
}

// ---------------- BN finalize / apply ----------------------------------------

__global__ void finalize_stats_kernel(const float* __restrict__ gsum,
                                      const float* __restrict__ gamma,
                                      const float* __restrict__ beta,
                                      float* __restrict__ sf, float invN) {
    int c = threadIdx.x;
    float mu = gsum[c] * invN;
    float var = gsum[128 + c] * invN - mu * mu;
    float rstd = rsqrtf(var + 1e-5f);
    float scale = gamma[c] * rstd;
    sf[c] = scale;
    sf[128 + c] = fmaf(-mu, scale, beta[c]);
}

__global__ void apply_bn_relu_kernel(float4* __restrict__ out,
                                     const float* __restrict__ sf, int total4) {
    int i = blockIdx.x * blockDim.x + threadIdx.x;
    if (i >= total4) return;
    int c = (i * 4) & 127;
    float4 v = out[i];
    v.x = fmaxf(fmaf(v.x, sf[c + 0], sf[128 + c + 0]), 0.f);
    v.y = fmaxf(fmaf(v.y, sf[c + 1], sf[128 + c + 1]), 0.f);
    v.z = fmaxf(fmaf(v.z, sf[c + 2], sf[128 + c + 2]), 0.f);
    v.w = fmaxf(fmaf(v.w, sf[c + 3], sf[128 + c + 3]), 0.f);
    out[i] = v;
}

// ---------------- launch -----------------------------------------------------

extern "C" void kernel_launch(void* const* d_in, const int* in_sizes, int n_in,
                              void* d_out, int out_size) {
    const float* h    = (const float*)d_in[0];
    const int*  esrc  = (const int*)d_in[1];
    const int*  edst  = (const int*)d_in[2];
    const float* W1   = (const float*)d_in[3];
    const float* b1   = (const float*)d_in[4];
    const float* g1   = (const float*)d_in[5];
    const float* be1  = (const float*)d_in[6];
    const float* W2   = (const float*)d_in[7];
    const float* b2   = (const float*)d_in[8];
    const float* g2   = (const float*)d_in[9];
    const float* be2  = (const float*)d_in[10];
    const float* eps  = (const float*)d_in[11];

    int N = in_sizes[0] / DF;
    int E = in_sizes[1];
    float* out = (float*)d_out;

    float* pooled = nullptr;
    float* y1 = nullptr;
    float* stats = nullptr;
    float* sf1 = nullptr;
    float* sf2 = nullptr;
    cudaGetSymbolAddress((void**)&pooled, g_pooled);
    cudaGetSymbolAddress((void**)&y1,     g_y1);
    cudaGetSymbolAddress((void**)&stats,  g_stats);
    cudaGetSymbolAddress((void**)&sf1,    g_sf1);
    cudaGetSymbolAddress((void**)&sf2,    g_sf2);

    cudaFuncSetAttribute(gemm_bf16_kernel<false>,
                         cudaFuncAttributeMaxDynamicSharedMemorySize, GEMM_SMEM_BYTES);
    cudaFuncSetAttribute(gemm_bf16_kernel<true>,
                         cudaFuncAttributeMaxDynamicSharedMemorySize, GEMM_SMEM_BYTES);

    int total4 = N * (DF / 4);
    int scanTotal = N + 1;
    int NB = (scanTotal + 1023) / 1024;

    // 1) init (stats + degree zero)                              [launch 1]
    init_kernel<<<(scanTotal + 255) / 256, 256>>>(scanTotal);
    // 2) CSR histogram                                           [launch 2]
    count_kernel<<<(E + 255) / 256, 256>>>(edst, E);
    // 3) scan                                                    [launch 3,4]
    scan_block_sums<<<NB, 256>>>(scanTotal);
    scan_final<<<NB, 1024>>>(scanTotal);
    // 4) bucket fill                                             [launch 5]
    fill_kernel<<<(E + 255) / 256, 256>>>(esrc, edst, E);
    // 5) gather-pool                                             [launch 6 - profiled]
    long long gthreads = (long long)N * 32;
    gather_kernel<<<(int)((gthreads + 255) / 256), 256>>>(
        (const float4*)h, eps, N);

    // 6) y1 = pooled @ W1 + b1, fused BN1 stats
    int gblocks = (N + 127) / 128;
    gemm_bf16_kernel<false><<<gblocks, 256, GEMM_SMEM_BYTES>>>(
        pooled, W1, b1, nullptr, y1, stats, N);
    finalize_stats_kernel<<<1, 128>>>(stats, g1, be1, sf1, 1.f / (float)N);

    // 7) out = relu(bn1(y1)) @ W2 + b2, fused BN2 stats
    gemm_bf16_kernel<true><<<gblocks, 256, GEMM_SMEM_BYTES>>>(
        y1, W2, b2, sf1, out, stats + 256, N);
    finalize_stats_kernel<<<1, 128>>>(stats + 256, g2, be2, sf2, 1.f / (float)N);

    // 8) out = relu(bn2(out))
    apply_bn_relu_kernel<<<(total4 + 255) / 256, 256>>>((float4*)out, sf2, total4);
}